// round 16
// baseline (speedup 1.0000x reference)
#include <cuda_runtime.h>
#include <cuda_bf16.h>
#include <math.h>
#include <stdint.h>

#define D   256
#define NB  65536
#define NR  131072
#define CF  128
#define CR  512
#define HB  64     // hist blocks per branch
#define SEG 4      // classsum segments per class
#define EPSN  1e-12f
// (1/T) * log2(e)
#define SC2 4.8089834696296117f
#define LN2 0.6931471805599453f

// ---------------- scratch (static device globals; no runtime alloc) ----------------
__device__ int   g_ph_f[HB*CF];    // per-block partial histograms (fully overwritten)
__device__ int   g_ph_r[HB*CR];
__device__ int   g_cnt_f[CF];
__device__ int   g_cnt_r[CR];
__device__ int   g_off_f[CF];
__device__ int   g_off_r[CR];
__device__ int   g_cur_f[CF];
__device__ int   g_cur_r[CR];
__device__ int   g_srt_f[NB];
__device__ int   g_srt_r[NR];
__device__ float g_sum_f[SEG*CF*D];   // per-segment partial class sums
__device__ float g_sum_r[SEG*CR*D];
__device__ int8_t g_xq_f[NB*D];    // quantized features (written by classsum)
__device__ int8_t g_xq_r[NR*D];
__device__ float  g_xs_f[NB];      // fused per-row scale SC2*inv*mx/127
__device__ float  g_xs_r[NR];
__device__ int8_t g_pbq_f[CF*D];   // updated prototypes, int8
__device__ int8_t g_pbq_r[CR*D];
__device__ float  g_pbs_f[CF];     // per-class dequant scale (max/127)
__device__ float  g_pbs_r[CR];
__device__ float g_ls_f[NB/128];
__device__ float g_lc_f[NB/128];
__device__ float g_ls_r[NR/128];
__device__ float g_lc_r[NR/128];

__device__ __forceinline__ uint32_t smem_u32(const void* p) {
    uint32_t a;
    asm("{ .reg .u64 t; cvta.to.shared.u64 t, %1; cvt.u32.u64 %0, t; }" : "=r"(a) : "l"(p));
    return a;
}
__device__ __forceinline__ float ex2f_fast(float x) {
    float r; asm("ex2.approx.f32 %0, %1;" : "=f"(r) : "f"(x)); return r;
}
__device__ __forceinline__ float lg2f_fast(float x) {
    float r; asm("lg2.approx.f32 %0, %1;" : "=f"(r) : "f"(x)); return r;
}
// exact int->float for |x| < 2^22 without the convert pipe (IADD + FSUB)
#define IMAGIC 0x4B400000
#define FMAGIC 12582912.0f
__device__ __forceinline__ float i2f_fast(int x) {
    return __int_as_float(x + IMAGIC) - FMAGIC;
}

#define LDSM_X4(r, addr) \
    asm volatile("ldmatrix.sync.aligned.m8n8.x4.shared.b16 {%0,%1,%2,%3}, [%4];" \
        : "=r"((r)[0]), "=r"((r)[1]), "=r"((r)[2]), "=r"((r)[3]) : "r"(addr))

__device__ __forceinline__ void mma_s8(int* c, const uint32_t* a, const uint32_t* b) {
    asm volatile(
        "mma.sync.aligned.m16n8k32.row.col.s32.s8.s8.s32 "
        "{%0,%1,%2,%3}, {%4,%5,%6,%7}, {%8,%9}, {%0,%1,%2,%3};"
        : "+r"(c[0]), "+r"(c[1]), "+r"(c[2]), "+r"(c[3])
        : "r"(a[0]), "r"(a[1]), "r"(a[2]), "r"(a[3]), "r"(b[0]), "r"(b[1]));
}

#define CP_COMMIT() asm volatile("cp.async.commit_group;" ::: "memory")
#define CP_WAIT0()  asm volatile("cp.async.wait_group 0;" ::: "memory")

// ---------------- partial histograms: no global atomics, nothing to zero ----------------
__global__ __launch_bounds__(256) void k_histp(
    const int* __restrict__ tlab, const int* __restrict__ nlab)
{
    __shared__ int sh[CR];
    bool fti = blockIdx.x < HB;
    const int* lab = fti ? tlab : nlab;
    int n = fti ? NB : NR;
    int C = fti ? CF : CR;
    int b = fti ? blockIdx.x : blockIdx.x - HB;
    int tid = threadIdx.x;
    for (int i = tid; i < C; i += 256) sh[i] = 0;
    __syncthreads();
    for (int i = b * 256 + tid; i < n; i += HB * 256) {
        int l = lab[i];
        if (l >= 0) atomicAdd(&sh[l], 1);
    }
    __syncthreads();
    int* dst = fti ? (g_ph_f + b * CF) : (g_ph_r + b * CR);
    for (int i = tid; i < C; i += 256) dst[i] = sh[i];
}

// ---------------- sum partials + exclusive scan (1 block) ----------------
__global__ void k_scan() {
    __shared__ int sh[CR];
    int t = threadIdx.x;
    int myc_f = 0, myc_r = 0;
    if (t < CF) {
        int s = 0;
        #pragma unroll 8
        for (int j = 0; j < HB; j++) s += g_ph_f[j * CF + t];
        myc_f = s; g_cnt_f[t] = s; sh[t] = s;
    }
    __syncthreads();
    for (int o = 1; o < CF; o <<= 1) {
        int v = (t < CF && t >= o) ? sh[t - o] : 0;
        __syncthreads();
        if (t < CF) sh[t] += v;
        __syncthreads();
    }
    if (t < CF) { int e = sh[t] - myc_f; g_off_f[t] = e; g_cur_f[t] = e; }
    __syncthreads();
    if (t < CR) {
        int s = 0;
        #pragma unroll 8
        for (int j = 0; j < HB; j++) s += g_ph_r[j * CR + t];
        myc_r = s; g_cnt_r[t] = s; sh[t] = s;
    }
    __syncthreads();
    for (int o = 1; o < CR; o <<= 1) {
        int v = (t < CR && t >= o) ? sh[t - o] : 0;
        __syncthreads();
        if (t < CR) sh[t] += v;
        __syncthreads();
    }
    if (t < CR) { int e = sh[t] - myc_r; g_off_r[t] = e; g_cur_r[t] = e; }
}

// ---------------- warp-aggregated scatter ----------------
__global__ void k_scatter2(const int* __restrict__ tlab, const int* __restrict__ nlab) {
    int i = blockIdx.x * blockDim.x + threadIdx.x;
    int lane = threadIdx.x & 31;
    int idx, l;
    int* cur;
    int* srt;
    if (i < NB) { idx = i;      l = tlab[idx]; cur = g_cur_f; srt = g_srt_f; }
    else        { idx = i - NB; l = nlab[idx]; cur = g_cur_r; srt = g_srt_r; }
    if (l >= 0) {
        unsigned am   = __activemask();
        unsigned mask = __match_any_sync(am, l);
        int leader = __ffs(mask) - 1;
        int rank   = __popc(mask & ((1u << lane) - 1));
        int base = 0;
        if (lane == leader) base = atomicAdd(&cur[l], __popc(mask));
        base = __shfl_sync(mask, base, leader);
        srt[base + rank] = idx;
    }
}

// ---------------- segmented classsum + X int8 quantization ----------------
__global__ __launch_bounds__(256) void k_classsum2(
    const float* __restrict__ Xf, const float* __restrict__ Xr)
{
    __shared__ float sh[8][256];
    int bi  = blockIdx.x;
    int seg = bi & (SEG - 1);
    int cc  = bi >> 2;
    bool fti = cc < CF;
    int c = fti ? cc : cc - CF;
    int C = fti ? CF : CR;
    const float* x   = fti ? Xf : Xr;
    const int*   srt = fti ? g_srt_f : g_srt_r;
    int s0 = fti ? g_off_f[c] : g_off_r[c];
    int n  = fti ? g_cnt_f[c] : g_cnt_r[c];
    float* sums = (fti ? g_sum_f : g_sum_r) + ((size_t)seg * C + c) * D;
    int8_t* xq  = fti ? g_xq_f : g_xq_r;
    float*  xs  = fti ? g_xs_f : g_xs_r;

    int a = (n * seg) / SEG;
    int b = (n * (seg + 1)) / SEG;
    int m = b - a;
    const int* seg_srt = srt + s0 + a;

    int tid = threadIdx.x, w = tid >> 5, lane = tid & 31;
    float a0 = 0.f, a1 = 0.f, a2 = 0.f, a3 = 0.f;
    float b0 = 0.f, b1 = 0.f, b2 = 0.f, b3 = 0.f;

    int i = w;
    for (; i + 8 < m; i += 16) {
        int idx1 = seg_srt[i];
        int idx2 = seg_srt[i + 8];
        const float4* r1 = (const float4*)(x + (size_t)idx1 * D);
        const float4* r2 = (const float4*)(x + (size_t)idx2 * D);
        float4 fa1 = r1[lane], fb1 = r1[32 + lane];
        float4 fa2 = r2[lane], fb2 = r2[32 + lane];
        float ss1 = fa1.x*fa1.x + fa1.y*fa1.y + fa1.z*fa1.z + fa1.w*fa1.w
                  + fb1.x*fb1.x + fb1.y*fb1.y + fb1.z*fb1.z + fb1.w*fb1.w;
        float ss2 = fa2.x*fa2.x + fa2.y*fa2.y + fa2.z*fa2.z + fa2.w*fa2.w
                  + fb2.x*fb2.x + fb2.y*fb2.y + fb2.z*fb2.z + fb2.w*fb2.w;
        float mx1 = fmaxf(fmaxf(fmaxf(fabsf(fa1.x), fabsf(fa1.y)), fmaxf(fabsf(fa1.z), fabsf(fa1.w))),
                          fmaxf(fmaxf(fabsf(fb1.x), fabsf(fb1.y)), fmaxf(fabsf(fb1.z), fabsf(fb1.w))));
        float mx2 = fmaxf(fmaxf(fmaxf(fabsf(fa2.x), fabsf(fa2.y)), fmaxf(fabsf(fa2.z), fabsf(fa2.w))),
                          fmaxf(fmaxf(fabsf(fb2.x), fabsf(fb2.y)), fmaxf(fabsf(fb2.z), fabsf(fb2.w))));
        #pragma unroll
        for (int o = 16; o; o >>= 1) {
            ss1 += __shfl_xor_sync(0xffffffffu, ss1, o);
            ss2 += __shfl_xor_sync(0xffffffffu, ss2, o);
            mx1  = fmaxf(mx1, __shfl_xor_sync(0xffffffffu, mx1, o));
            mx2  = fmaxf(mx2, __shfl_xor_sync(0xffffffffu, mx2, o));
        }
        mx1 = fmaxf(mx1, 1e-30f); mx2 = fmaxf(mx2, 1e-30f);
        float inv1 = 1.0f / fmaxf(sqrtf(ss1), EPSN);
        float inv2 = 1.0f / fmaxf(sqrtf(ss2), EPSN);
        float qs1 = 127.f / mx1, qs2 = 127.f / mx2;
        {
            int q0 = __float2int_rn(fa1.x * qs1), q1 = __float2int_rn(fa1.y * qs1);
            int q2 = __float2int_rn(fa1.z * qs1), q3 = __float2int_rn(fa1.w * qs1);
            int q4 = __float2int_rn(fb1.x * qs1), q5 = __float2int_rn(fb1.y * qs1);
            int q6 = __float2int_rn(fb1.z * qs1), q7 = __float2int_rn(fb1.w * qs1);
            uint32_t p0 = (q0 & 0xFF) | ((q1 & 0xFF) << 8) | ((q2 & 0xFF) << 16) | ((q3 & 0xFF) << 24);
            uint32_t p1 = (q4 & 0xFF) | ((q5 & 0xFF) << 8) | ((q6 & 0xFF) << 16) | ((q7 & 0xFF) << 24);
            uint32_t* orow = (uint32_t*)(xq + (size_t)idx1 * D);
            orow[lane] = p0; orow[32 + lane] = p1;
            if (lane == 0) xs[idx1] = SC2 * inv1 * mx1 * (1.f / 127.f);
        }
        {
            int q0 = __float2int_rn(fa2.x * qs2), q1 = __float2int_rn(fa2.y * qs2);
            int q2 = __float2int_rn(fa2.z * qs2), q3 = __float2int_rn(fa2.w * qs2);
            int q4 = __float2int_rn(fb2.x * qs2), q5 = __float2int_rn(fb2.y * qs2);
            int q6 = __float2int_rn(fb2.z * qs2), q7 = __float2int_rn(fb2.w * qs2);
            uint32_t p0 = (q0 & 0xFF) | ((q1 & 0xFF) << 8) | ((q2 & 0xFF) << 16) | ((q3 & 0xFF) << 24);
            uint32_t p1 = (q4 & 0xFF) | ((q5 & 0xFF) << 8) | ((q6 & 0xFF) << 16) | ((q7 & 0xFF) << 24);
            uint32_t* orow = (uint32_t*)(xq + (size_t)idx2 * D);
            orow[lane] = p0; orow[32 + lane] = p1;
            if (lane == 0) xs[idx2] = SC2 * inv2 * mx2 * (1.f / 127.f);
        }
        a0 += fa1.x * inv1 + fa2.x * inv2; a1 += fa1.y * inv1 + fa2.y * inv2;
        a2 += fa1.z * inv1 + fa2.z * inv2; a3 += fa1.w * inv1 + fa2.w * inv2;
        b0 += fb1.x * inv1 + fb2.x * inv2; b1 += fb1.y * inv1 + fb2.y * inv2;
        b2 += fb1.z * inv1 + fb2.z * inv2; b3 += fb1.w * inv1 + fb2.w * inv2;
    }
    for (; i < m; i += 8) {
        int idx = seg_srt[i];
        const float4* row = (const float4*)(x + (size_t)idx * D);
        float4 fa = row[lane];
        float4 fb = row[32 + lane];
        float ss = fa.x*fa.x + fa.y*fa.y + fa.z*fa.z + fa.w*fa.w
                 + fb.x*fb.x + fb.y*fb.y + fb.z*fb.z + fb.w*fb.w;
        float mx = fmaxf(fmaxf(fmaxf(fabsf(fa.x), fabsf(fa.y)), fmaxf(fabsf(fa.z), fabsf(fa.w))),
                         fmaxf(fmaxf(fabsf(fb.x), fabsf(fb.y)), fmaxf(fabsf(fb.z), fabsf(fb.w))));
        #pragma unroll
        for (int o = 16; o; o >>= 1) {
            ss += __shfl_xor_sync(0xffffffffu, ss, o);
            mx  = fmaxf(mx, __shfl_xor_sync(0xffffffffu, mx, o));
        }
        mx = fmaxf(mx, 1e-30f);
        float inv = 1.0f / fmaxf(sqrtf(ss), EPSN);
        float qs = 127.f / mx;
        int q0 = __float2int_rn(fa.x * qs), q1 = __float2int_rn(fa.y * qs);
        int q2 = __float2int_rn(fa.z * qs), q3 = __float2int_rn(fa.w * qs);
        int q4 = __float2int_rn(fb.x * qs), q5 = __float2int_rn(fb.y * qs);
        int q6 = __float2int_rn(fb.z * qs), q7 = __float2int_rn(fb.w * qs);
        uint32_t p0 = (q0 & 0xFF) | ((q1 & 0xFF) << 8) | ((q2 & 0xFF) << 16) | ((q3 & 0xFF) << 24);
        uint32_t p1 = (q4 & 0xFF) | ((q5 & 0xFF) << 8) | ((q6 & 0xFF) << 16) | ((q7 & 0xFF) << 24);
        uint32_t* orow = (uint32_t*)(xq + (size_t)idx * D);
        orow[lane] = p0; orow[32 + lane] = p1;
        if (lane == 0) xs[idx] = SC2 * inv * mx * (1.f / 127.f);
        a0 += fa.x * inv; a1 += fa.y * inv; a2 += fa.z * inv; a3 += fa.w * inv;
        b0 += fb.x * inv; b1 += fb.y * inv; b2 += fb.z * inv; b3 += fb.w * inv;
    }
    sh[w][lane * 4 + 0] = a0; sh[w][lane * 4 + 1] = a1;
    sh[w][lane * 4 + 2] = a2; sh[w][lane * 4 + 3] = a3;
    sh[w][128 + lane * 4 + 0] = b0; sh[w][128 + lane * 4 + 1] = b1;
    sh[w][128 + lane * 4 + 2] = b2; sh[w][128 + lane * 4 + 3] = b3;
    __syncthreads();
    float s = 0.f;
    #pragma unroll
    for (int ww = 0; ww < 8; ww++) s += sh[ww][tid];
    sums[tid] = s;
}

// ---------------- fused prototype EMA update -> int8 + per-class scale ----------------
__global__ __launch_bounds__(256) void k_proto2(
    const float* __restrict__ pf, const float* __restrict__ pr)
{
    __shared__ float sh[256];
    bool fti = blockIdx.x < CF;
    int c = fti ? blockIdx.x : blockIdx.x - CF;
    int C = fti ? CF : CR;
    int n = fti ? g_cnt_f[c] : g_cnt_r[c];
    const float* sums = (fti ? g_sum_f : g_sum_r);
    const float* pin  = (fti ? pf : pr) + c * D;
    int8_t* pout = (fti ? g_pbq_f : g_pbq_r) + c * D;
    float*  psc  = fti ? g_pbs_f : g_pbs_r;

    int t = threadIdx.x;
    float acc = 0.f;
    #pragma unroll
    for (int seg = 0; seg < SEG; seg++)
        acc += sums[((size_t)seg * C + c) * D + t];
    float mv = acc / fmaxf((float)n, 1.f);
    sh[t] = mv * mv;
    __syncthreads();
    #pragma unroll
    for (int o = 128; o; o >>= 1) { if (t < o) sh[t] += sh[t + o]; __syncthreads(); }
    float nm = fmaxf(sqrtf(sh[0]), EPSN);
    __syncthreads();
    mv = mv / nm;
    float p = pin[t];
    float q = 0.5f * p + 0.5f * mv;
    sh[t] = q * q;
    __syncthreads();
    #pragma unroll
    for (int o = 128; o; o >>= 1) { if (t < o) sh[t] += sh[t + o]; __syncthreads(); }
    float nq = fmaxf(sqrtf(sh[0]), EPSN);
    float val = (n > 0) ? q / nq : p;
    __syncthreads();
    sh[t] = fabsf(val);
    __syncthreads();
    #pragma unroll
    for (int o = 128; o; o >>= 1) { if (t < o) sh[t] = fmaxf(sh[t], sh[t + o]); __syncthreads(); }
    float m = fmaxf(sh[0], 1e-30f);
    int qv = __float2int_rn(val * (127.f / m));
    qv = max(-127, min(127, qv));
    pout[t] = (int8_t)qv;
    if (t == 0) psc[c] = m * (1.f / 127.f);
}

// ---------------- int8 mma.sync fused GEMM + softmax CE ----------------
// smem: 0 lab | 512 scale | 1024 rs | 2048 tg | 3072 red | 3200 scb[512]
//       5376 A(34816) | 40192 B0(34816) | 75008 B1(34816) -> 109824 (2 CTA/SM)
#define A_OFF   5376
#define B0_OFF  40192
#define BBUF    34816
#define SMEM_LOSS 109824
#define NBLK_R (NR/128)

__device__ __forceinline__ void prefetch_T(uint32_t sbu, uint32_t dstOff,
                                           const int8_t* __restrict__ P,
                                           int r0, int tid) {
    #pragma unroll
    for (int i = 0; i < 8; i++) {
        int ch = tid + i * 256;
        int r  = ch >> 4;
        int c16 = (ch & 15) * 16;
        uint32_t dst = sbu + dstOff + (uint32_t)(r * 272 + c16);
        const void* src = P + (size_t)(r0 + r) * D + c16;
        asm volatile("cp.async.cg.shared.global [%0], [%1], 16;" :: "r"(dst), "l"(src));
    }
}

__global__ __launch_bounds__(256, 2)
void k_loss_tc(const int* __restrict__ tlab, const int* __restrict__ nlab)
{
    extern __shared__ char smem[];
    int*   lab_sm   = (int*)(smem + 0);
    float* scale_sm = (float*)(smem + 512);
    float* rs_sm    = (float*)(smem + 1024);
    float* tg_sm    = (float*)(smem + 2048);
    float* red_s    = (float*)(smem + 3072);
    float* red_c    = (float*)(smem + 3104);
    float* scb_sm   = (float*)(smem + 3200);

    const bool fti = blockIdx.x >= NBLK_R;
    const int  bid = fti ? blockIdx.x - NBLK_R : blockIdx.x;
    const int8_t* Xq = fti ? g_xq_f : g_xq_r;
    const float*  Xs = fti ? g_xs_f : g_xs_r;
    const int8_t* Pq = fti ? g_pbq_f : g_pbq_r;
    const float*  Ps = fti ? g_pbs_f : g_pbs_r;
    const int* lab = fti ? tlab : nlab;
    float* lsum = fti ? g_ls_f : g_ls_r;
    float* lcnt = fti ? g_lc_f : g_lc_r;
    const int NCH = fti ? (CF / 128) : (CR / 128);

    const int tid  = threadIdx.x;
    const int wid  = tid >> 5;
    const int lane = tid & 31;
    const int wr   = wid & 3;
    const int wc   = wid >> 2;
    const int row0 = bid * 128;
    const uint32_t sbu = smem_u32(smem);

    prefetch_T(sbu, A_OFF, Xq, row0, tid);
    prefetch_T(sbu, B0_OFF, Pq, 0, tid);
    CP_COMMIT();
    if (tid < 128) {
        lab_sm[tid]   = lab[row0 + tid];
        scale_sm[tid] = Xs[row0 + tid];
    }
    for (int i = tid; i < NCH * 128; i += 256) scb_sm[i] = Ps[i];
    CP_WAIT0();
    __syncthreads();

    int lb4[4]; float sc4[4];
    #pragma unroll
    for (int mt = 0; mt < 2; mt++)
        #pragma unroll
        for (int h = 0; h < 2; h++) {
            int r = wr * 32 + mt * 16 + (lane >> 2) + h * 8;
            lb4[mt * 2 + h] = lab_sm[r];
            sc4[mt * 2 + h] = scale_sm[r];
        }

    const uint32_t aBase = sbu + A_OFF
        + (uint32_t)(wr * 32 + (lane & 15)) * 272 + (uint32_t)(lane >> 4) * 16;
    const uint32_t bB0 = sbu + B0_OFF
        + (uint32_t)(wc * 64 + (lane & 7) + ((lane >> 4) & 1) * 8) * 272
        + (uint32_t)((lane >> 3) & 1) * 16;

    float ssum[4] = {0.f, 0.f, 0.f, 0.f};
    float tgt[4]  = {0.f, 0.f, 0.f, 0.f};

    for (int c = 0; c < NCH; c++) {
        if (c) { CP_WAIT0(); __syncthreads(); }
        if (c + 1 < NCH) {
            prefetch_T(sbu, B0_OFF + (uint32_t)((c + 1) & 1) * BBUF, Pq, (c + 1) * 128, tid);
            CP_COMMIT();
        }
        const uint32_t bBase = bB0 + (uint32_t)(c & 1) * BBUF;

        int acc[2][8][4];
        #pragma unroll
        for (int mt = 0; mt < 2; mt++)
            #pragma unroll
            for (int nt = 0; nt < 8; nt++)
                #pragma unroll
                for (int e = 0; e < 4; e++) acc[mt][nt][e] = 0;

        #pragma unroll
        for (int k = 0; k < 8; k++) {
            uint32_t aoff = (uint32_t)k * 32;
            uint32_t ah0[4], ah1[4];
            LDSM_X4(ah0, aBase + aoff);
            LDSM_X4(ah1, aBase + 4352 + aoff);
            #pragma unroll
            for (int ntp = 0; ntp < 4; ntp++) {
                uint32_t bh[4];
                LDSM_X4(bh, bBase + (uint32_t)ntp * 4352 + aoff);
                mma_s8(acc[0][ntp*2],   ah0, bh);
                mma_s8(acc[1][ntp*2],   ah1, bh);
                mma_s8(acc[0][ntp*2+1], ah0, bh + 2);
                mma_s8(acc[1][ntp*2+1], ah1, bh + 2);
            }
        }

        // ---- epilogue: cvt-pipe-free int->float (IADD+FSUB), then scale+ex2 ----
        int c0 = c * 128;
        #pragma unroll
        for (int nt = 0; nt < 8; nt++) {
            int colb = c0 + wc * 64 + nt * 8 + (lane & 3) * 2;
            float sb0 = scb_sm[colb];
            float sb1 = scb_sm[colb + 1];
            #pragma unroll
            for (int mt = 0; mt < 2; mt++) {
                float sA = sc4[mt*2], sB = sc4[mt*2+1];
                float s0 = sA * sb0, s1 = sA * sb1;
                float s2 = sB * sb0, s3 = sB * sb1;
                float l0 = i2f_fast(acc[mt][nt][0]) * s0;
                float l1 = i2f_fast(acc[mt][nt][1]) * s1;
                float l2 = i2f_fast(acc[mt][nt][2]) * s2;
                float l3 = i2f_fast(acc[mt][nt][3]) * s3;
                ssum[mt*2]   += ex2f_fast(l0) + ex2f_fast(l1);
                ssum[mt*2+1] += ex2f_fast(l2) + ex2f_fast(l3);
                if (lb4[mt*2]   == colb)     tgt[mt*2]   = l0;
                if (lb4[mt*2]   == colb + 1) tgt[mt*2]   = l1;
                if (lb4[mt*2+1] == colb)     tgt[mt*2+1] = l2;
                if (lb4[mt*2+1] == colb + 1) tgt[mt*2+1] = l3;
            }
        }
    }

    #pragma unroll
    for (int i = 0; i < 4; i++) {
        ssum[i] += __shfl_xor_sync(0xffffffffu, ssum[i], 1);
        ssum[i] += __shfl_xor_sync(0xffffffffu, ssum[i], 2);
        tgt[i]  += __shfl_xor_sync(0xffffffffu, tgt[i], 1);
        tgt[i]  += __shfl_xor_sync(0xffffffffu, tgt[i], 2);
    }
    if ((lane & 3) == 0) {
        #pragma unroll
        for (int i = 0; i < 4; i++) {
            int r = wr * 32 + (i >> 1) * 16 + (lane >> 2) + (i & 1) * 8;
            rs_sm[r * 2 + wc] = ssum[i];
            tg_sm[r * 2 + wc] = tgt[i];
        }
    }
    __syncthreads();

    float v = 0.f, cn = 0.f;
    if (tid < 128) {
        int lb = lab_sm[tid];
        if (lb >= 0) {
            float S  = rs_sm[tid * 2] + rs_sm[tid * 2 + 1];
            float T2 = tg_sm[tid * 2] + tg_sm[tid * 2 + 1];
            v  = LN2 * (lg2f_fast(S) - T2);
            cn = 1.f;
        }
    }
    #pragma unroll
    for (int o = 16; o; o >>= 1) {
        v  += __shfl_xor_sync(0xffffffffu, v, o);
        cn += __shfl_xor_sync(0xffffffffu, cn, o);
    }
    if (lane == 0) { red_s[wid] = v; red_c[wid] = cn; }
    __syncthreads();
    if (tid == 0) {
        lsum[bid] = red_s[0] + red_s[1] + red_s[2] + red_s[3];
        lcnt[bid] = red_c[0] + red_c[1] + red_c[2] + red_c[3];
    }
}

// ---------------- final reduction of per-block partials ----------------
__global__ void k_final(float* __restrict__ out) {
    __shared__ float sh[1024];
    int t = threadIdx.x;
    float v;

    v = (t < NB / 128) ? g_ls_f[t] : 0.f;
    sh[t] = v; __syncthreads();
    #pragma unroll
    for (int o = 512; o; o >>= 1) { if (t < o) sh[t] += sh[t + o]; __syncthreads(); }
    float sf = sh[0]; __syncthreads();

    v = (t < NB / 128) ? g_lc_f[t] : 0.f;
    sh[t] = v; __syncthreads();
    #pragma unroll
    for (int o = 512; o; o >>= 1) { if (t < o) sh[t] += sh[t + o]; __syncthreads(); }
    float cf = sh[0]; __syncthreads();

    v = g_ls_r[t];
    sh[t] = v; __syncthreads();
    #pragma unroll
    for (int o = 512; o; o >>= 1) { if (t < o) sh[t] += sh[t + o]; __syncthreads(); }
    float sr = sh[0]; __syncthreads();

    v = g_lc_r[t];
    sh[t] = v; __syncthreads();
    #pragma unroll
    for (int o = 512; o; o >>= 1) { if (t < o) sh[t] += sh[t + o]; __syncthreads(); }
    float cr = sh[0];

    if (t == 0) {
        out[0] = sf / fmaxf(cf, 1.f);
        out[1] = sr / fmaxf(cr, 1.f);
    }
}

// ---------------- host launcher (graph-capturable, allocation-free) ----------------
extern "C" void kernel_launch(void* const* d_in, const int* in_sizes, int n_in,
                              void* d_out, int out_size) {
    (void)in_sizes; (void)n_in; (void)out_size;
    const float* f_fti = (const float*)d_in[0];
    const float* e_rcl = (const float*)d_in[1];
    const int*   tlab  = (const int*)d_in[2];
    const int*   nlab  = (const int*)d_in[3];
    const float* pf    = (const float*)d_in[4];
    const float* pr    = (const float*)d_in[5];
    float* out = (float*)d_out;

    cudaFuncSetAttribute(k_loss_tc, cudaFuncAttributeMaxDynamicSharedMemorySize, SMEM_LOSS);

    k_histp<<<2 * HB, 256>>>(tlab, nlab);
    k_scan<<<1, 512>>>();
    k_scatter2<<<(NB + NR) / 256, 256>>>(tlab, nlab);
    k_classsum2<<<SEG * (CF + CR), 256>>>(f_fti, e_rcl);
    k_proto2<<<CF + CR, 256>>>(pf, pr);
    k_loss_tc<<<NR / 128 + NB / 128, 256, SMEM_LOSS>>>(tlab, nlab);
    k_final<<<1, 1024>>>(out);
}

// round 17
// speedup vs baseline: 1.0413x; 1.0413x over previous
#include <cuda_runtime.h>
#include <cuda_bf16.h>
#include <math.h>
#include <stdint.h>

#define D   256
#define NB  65536
#define NR  131072
#define CF  128
#define CR  512
#define HB  64     // hist blocks per branch
#define SEG 4      // classsum segments per class
#define EPSN  1e-12f
// (1/T) * log2(e)
#define SC2 4.8089834696296117f
#define LN2 0.6931471805599453f

// ---------------- scratch (static device globals; no runtime alloc) ----------------
__device__ int   g_ph_f[HB*CF];    // per-block partial histograms (fully overwritten)
__device__ int   g_ph_r[HB*CR];
__device__ int   g_cnt_f[CF];
__device__ int   g_cnt_r[CR];
__device__ int   g_off_f[CF];
__device__ int   g_off_r[CR];
__device__ int   g_cur_f[CF];
__device__ int   g_cur_r[CR];
__device__ int   g_srt_f[NB];
__device__ int   g_srt_r[NR];
__device__ float g_sum_f[SEG*CF*D];   // per-segment partial class sums
__device__ float g_sum_r[SEG*CR*D];
__device__ int8_t g_xq_f[NB*D];    // quantized features (written by classsum)
__device__ int8_t g_xq_r[NR*D];
__device__ float  g_xs_f[NB];      // fused per-row scale SC2*inv*mx/127
__device__ float  g_xs_r[NR];
__device__ int8_t g_pbq_f[CF*D];   // updated prototypes, int8
__device__ int8_t g_pbq_r[CR*D];
__device__ float  g_pbs_f[CF];     // per-class dequant scale (max/127)
__device__ float  g_pbs_r[CR];
__device__ float g_ls_f[NB/128];
__device__ float g_lc_f[NB/128];
__device__ float g_ls_r[NR/128];
__device__ float g_lc_r[NR/128];
__device__ int   g_done = 0;       // loss-CTA completion counter (finisher resets)

__device__ __forceinline__ uint32_t smem_u32(const void* p) {
    uint32_t a;
    asm("{ .reg .u64 t; cvta.to.shared.u64 t, %1; cvt.u32.u64 %0, t; }" : "=r"(a) : "l"(p));
    return a;
}
__device__ __forceinline__ float ex2f_fast(float x) {
    float r; asm("ex2.approx.f32 %0, %1;" : "=f"(r) : "f"(x)); return r;
}
__device__ __forceinline__ float lg2f_fast(float x) {
    float r; asm("lg2.approx.f32 %0, %1;" : "=f"(r) : "f"(x)); return r;
}

#define LDSM_X4(r, addr) \
    asm volatile("ldmatrix.sync.aligned.m8n8.x4.shared.b16 {%0,%1,%2,%3}, [%4];" \
        : "=r"((r)[0]), "=r"((r)[1]), "=r"((r)[2]), "=r"((r)[3]) : "r"(addr))

__device__ __forceinline__ void mma_s8(int* c, const uint32_t* a, const uint32_t* b) {
    asm volatile(
        "mma.sync.aligned.m16n8k32.row.col.s32.s8.s8.s32 "
        "{%0,%1,%2,%3}, {%4,%5,%6,%7}, {%8,%9}, {%0,%1,%2,%3};"
        : "+r"(c[0]), "+r"(c[1]), "+r"(c[2]), "+r"(c[3])
        : "r"(a[0]), "r"(a[1]), "r"(a[2]), "r"(a[3]), "r"(b[0]), "r"(b[1]));
}

#define CP_COMMIT() asm volatile("cp.async.commit_group;" ::: "memory")
#define CP_WAIT0()  asm volatile("cp.async.wait_group 0;" ::: "memory")

// ---------------- partial histograms: no global atomics, nothing to zero ----------------
__global__ __launch_bounds__(256) void k_histp(
    const int* __restrict__ tlab, const int* __restrict__ nlab)
{
    __shared__ int sh[CR];
    bool fti = blockIdx.x < HB;
    const int* lab = fti ? tlab : nlab;
    int n = fti ? NB : NR;
    int C = fti ? CF : CR;
    int b = fti ? blockIdx.x : blockIdx.x - HB;
    int tid = threadIdx.x;
    for (int i = tid; i < C; i += 256) sh[i] = 0;
    __syncthreads();
    for (int i = b * 256 + tid; i < n; i += HB * 256) {
        int l = lab[i];
        if (l >= 0) atomicAdd(&sh[l], 1);
    }
    __syncthreads();
    int* dst = fti ? (g_ph_f + b * CF) : (g_ph_r + b * CR);
    for (int i = tid; i < C; i += 256) dst[i] = sh[i];
}

// ---------------- sum partials + exclusive scan (1 block) ----------------
__global__ void k_scan() {
    __shared__ int sh[CR];
    int t = threadIdx.x;
    int myc_f = 0, myc_r = 0;
    if (t < CF) {
        int s = 0;
        #pragma unroll 8
        for (int j = 0; j < HB; j++) s += g_ph_f[j * CF + t];
        myc_f = s; g_cnt_f[t] = s; sh[t] = s;
    }
    __syncthreads();
    for (int o = 1; o < CF; o <<= 1) {
        int v = (t < CF && t >= o) ? sh[t - o] : 0;
        __syncthreads();
        if (t < CF) sh[t] += v;
        __syncthreads();
    }
    if (t < CF) { int e = sh[t] - myc_f; g_off_f[t] = e; g_cur_f[t] = e; }
    __syncthreads();
    if (t < CR) {
        int s = 0;
        #pragma unroll 8
        for (int j = 0; j < HB; j++) s += g_ph_r[j * CR + t];
        myc_r = s; g_cnt_r[t] = s; sh[t] = s;
    }
    __syncthreads();
    for (int o = 1; o < CR; o <<= 1) {
        int v = (t < CR && t >= o) ? sh[t - o] : 0;
        __syncthreads();
        if (t < CR) sh[t] += v;
        __syncthreads();
    }
    if (t < CR) { int e = sh[t] - myc_r; g_off_r[t] = e; g_cur_r[t] = e; }
}

// ---------------- warp-aggregated scatter ----------------
__global__ void k_scatter2(const int* __restrict__ tlab, const int* __restrict__ nlab) {
    int i = blockIdx.x * blockDim.x + threadIdx.x;
    int lane = threadIdx.x & 31;
    int idx, l;
    int* cur;
    int* srt;
    if (i < NB) { idx = i;      l = tlab[idx]; cur = g_cur_f; srt = g_srt_f; }
    else        { idx = i - NB; l = nlab[idx]; cur = g_cur_r; srt = g_srt_r; }
    if (l >= 0) {
        unsigned am   = __activemask();
        unsigned mask = __match_any_sync(am, l);
        int leader = __ffs(mask) - 1;
        int rank   = __popc(mask & ((1u << lane) - 1));
        int base = 0;
        if (lane == leader) base = atomicAdd(&cur[l], __popc(mask));
        base = __shfl_sync(mask, base, leader);
        srt[base + rank] = idx;
    }
}

// ---------------- segmented classsum + X int8 quantization ----------------
__global__ __launch_bounds__(256) void k_classsum2(
    const float* __restrict__ Xf, const float* __restrict__ Xr)
{
    __shared__ float sh[8][256];
    int bi  = blockIdx.x;
    int seg = bi & (SEG - 1);
    int cc  = bi >> 2;
    bool fti = cc < CF;
    int c = fti ? cc : cc - CF;
    int C = fti ? CF : CR;
    const float* x   = fti ? Xf : Xr;
    const int*   srt = fti ? g_srt_f : g_srt_r;
    int s0 = fti ? g_off_f[c] : g_off_r[c];
    int n  = fti ? g_cnt_f[c] : g_cnt_r[c];
    float* sums = (fti ? g_sum_f : g_sum_r) + ((size_t)seg * C + c) * D;
    int8_t* xq  = fti ? g_xq_f : g_xq_r;
    float*  xs  = fti ? g_xs_f : g_xs_r;

    int a = (n * seg) / SEG;
    int b = (n * (seg + 1)) / SEG;
    int m = b - a;
    const int* seg_srt = srt + s0 + a;

    int tid = threadIdx.x, w = tid >> 5, lane = tid & 31;
    float a0 = 0.f, a1 = 0.f, a2 = 0.f, a3 = 0.f;
    float b0 = 0.f, b1 = 0.f, b2 = 0.f, b3 = 0.f;

    int i = w;
    for (; i + 8 < m; i += 16) {
        int idx1 = seg_srt[i];
        int idx2 = seg_srt[i + 8];
        const float4* r1 = (const float4*)(x + (size_t)idx1 * D);
        const float4* r2 = (const float4*)(x + (size_t)idx2 * D);
        float4 fa1 = r1[lane], fb1 = r1[32 + lane];
        float4 fa2 = r2[lane], fb2 = r2[32 + lane];
        float ss1 = fa1.x*fa1.x + fa1.y*fa1.y + fa1.z*fa1.z + fa1.w*fa1.w
                  + fb1.x*fb1.x + fb1.y*fb1.y + fb1.z*fb1.z + fb1.w*fb1.w;
        float ss2 = fa2.x*fa2.x + fa2.y*fa2.y + fa2.z*fa2.z + fa2.w*fa2.w
                  + fb2.x*fb2.x + fb2.y*fb2.y + fb2.z*fb2.z + fb2.w*fb2.w;
        float mx1 = fmaxf(fmaxf(fmaxf(fabsf(fa1.x), fabsf(fa1.y)), fmaxf(fabsf(fa1.z), fabsf(fa1.w))),
                          fmaxf(fmaxf(fabsf(fb1.x), fabsf(fb1.y)), fmaxf(fabsf(fb1.z), fabsf(fb1.w))));
        float mx2 = fmaxf(fmaxf(fmaxf(fabsf(fa2.x), fabsf(fa2.y)), fmaxf(fabsf(fa2.z), fabsf(fa2.w))),
                          fmaxf(fmaxf(fabsf(fb2.x), fabsf(fb2.y)), fmaxf(fabsf(fb2.z), fabsf(fb2.w))));
        #pragma unroll
        for (int o = 16; o; o >>= 1) {
            ss1 += __shfl_xor_sync(0xffffffffu, ss1, o);
            ss2 += __shfl_xor_sync(0xffffffffu, ss2, o);
            mx1  = fmaxf(mx1, __shfl_xor_sync(0xffffffffu, mx1, o));
            mx2  = fmaxf(mx2, __shfl_xor_sync(0xffffffffu, mx2, o));
        }
        mx1 = fmaxf(mx1, 1e-30f); mx2 = fmaxf(mx2, 1e-30f);
        float inv1 = 1.0f / fmaxf(sqrtf(ss1), EPSN);
        float inv2 = 1.0f / fmaxf(sqrtf(ss2), EPSN);
        float qs1 = 127.f / mx1, qs2 = 127.f / mx2;
        {
            int q0 = __float2int_rn(fa1.x * qs1), q1 = __float2int_rn(fa1.y * qs1);
            int q2 = __float2int_rn(fa1.z * qs1), q3 = __float2int_rn(fa1.w * qs1);
            int q4 = __float2int_rn(fb1.x * qs1), q5 = __float2int_rn(fb1.y * qs1);
            int q6 = __float2int_rn(fb1.z * qs1), q7 = __float2int_rn(fb1.w * qs1);
            uint32_t p0 = (q0 & 0xFF) | ((q1 & 0xFF) << 8) | ((q2 & 0xFF) << 16) | ((q3 & 0xFF) << 24);
            uint32_t p1 = (q4 & 0xFF) | ((q5 & 0xFF) << 8) | ((q6 & 0xFF) << 16) | ((q7 & 0xFF) << 24);
            uint32_t* orow = (uint32_t*)(xq + (size_t)idx1 * D);
            orow[lane] = p0; orow[32 + lane] = p1;
            if (lane == 0) xs[idx1] = SC2 * inv1 * mx1 * (1.f / 127.f);
        }
        {
            int q0 = __float2int_rn(fa2.x * qs2), q1 = __float2int_rn(fa2.y * qs2);
            int q2 = __float2int_rn(fa2.z * qs2), q3 = __float2int_rn(fa2.w * qs2);
            int q4 = __float2int_rn(fb2.x * qs2), q5 = __float2int_rn(fb2.y * qs2);
            int q6 = __float2int_rn(fb2.z * qs2), q7 = __float2int_rn(fb2.w * qs2);
            uint32_t p0 = (q0 & 0xFF) | ((q1 & 0xFF) << 8) | ((q2 & 0xFF) << 16) | ((q3 & 0xFF) << 24);
            uint32_t p1 = (q4 & 0xFF) | ((q5 & 0xFF) << 8) | ((q6 & 0xFF) << 16) | ((q7 & 0xFF) << 24);
            uint32_t* orow = (uint32_t*)(xq + (size_t)idx2 * D);
            orow[lane] = p0; orow[32 + lane] = p1;
            if (lane == 0) xs[idx2] = SC2 * inv2 * mx2 * (1.f / 127.f);
        }
        a0 += fa1.x * inv1 + fa2.x * inv2; a1 += fa1.y * inv1 + fa2.y * inv2;
        a2 += fa1.z * inv1 + fa2.z * inv2; a3 += fa1.w * inv1 + fa2.w * inv2;
        b0 += fb1.x * inv1 + fb2.x * inv2; b1 += fb1.y * inv1 + fb2.y * inv2;
        b2 += fb1.z * inv1 + fb2.z * inv2; b3 += fb1.w * inv1 + fb2.w * inv2;
    }
    for (; i < m; i += 8) {
        int idx = seg_srt[i];
        const float4* row = (const float4*)(x + (size_t)idx * D);
        float4 fa = row[lane];
        float4 fb = row[32 + lane];
        float ss = fa.x*fa.x + fa.y*fa.y + fa.z*fa.z + fa.w*fa.w
                 + fb.x*fb.x + fb.y*fb.y + fb.z*fb.z + fb.w*fb.w;
        float mx = fmaxf(fmaxf(fmaxf(fabsf(fa.x), fabsf(fa.y)), fmaxf(fabsf(fa.z), fabsf(fa.w))),
                         fmaxf(fmaxf(fabsf(fb.x), fabsf(fb.y)), fmaxf(fabsf(fb.z), fabsf(fb.w))));
        #pragma unroll
        for (int o = 16; o; o >>= 1) {
            ss += __shfl_xor_sync(0xffffffffu, ss, o);
            mx  = fmaxf(mx, __shfl_xor_sync(0xffffffffu, mx, o));
        }
        mx = fmaxf(mx, 1e-30f);
        float inv = 1.0f / fmaxf(sqrtf(ss), EPSN);
        float qs = 127.f / mx;
        int q0 = __float2int_rn(fa.x * qs), q1 = __float2int_rn(fa.y * qs);
        int q2 = __float2int_rn(fa.z * qs), q3 = __float2int_rn(fa.w * qs);
        int q4 = __float2int_rn(fb.x * qs), q5 = __float2int_rn(fb.y * qs);
        int q6 = __float2int_rn(fb.z * qs), q7 = __float2int_rn(fb.w * qs);
        uint32_t p0 = (q0 & 0xFF) | ((q1 & 0xFF) << 8) | ((q2 & 0xFF) << 16) | ((q3 & 0xFF) << 24);
        uint32_t p1 = (q4 & 0xFF) | ((q5 & 0xFF) << 8) | ((q6 & 0xFF) << 16) | ((q7 & 0xFF) << 24);
        uint32_t* orow = (uint32_t*)(xq + (size_t)idx * D);
        orow[lane] = p0; orow[32 + lane] = p1;
        if (lane == 0) xs[idx] = SC2 * inv * mx * (1.f / 127.f);
        a0 += fa.x * inv; a1 += fa.y * inv; a2 += fa.z * inv; a3 += fa.w * inv;
        b0 += fb.x * inv; b1 += fb.y * inv; b2 += fb.z * inv; b3 += fb.w * inv;
    }
    sh[w][lane * 4 + 0] = a0; sh[w][lane * 4 + 1] = a1;
    sh[w][lane * 4 + 2] = a2; sh[w][lane * 4 + 3] = a3;
    sh[w][128 + lane * 4 + 0] = b0; sh[w][128 + lane * 4 + 1] = b1;
    sh[w][128 + lane * 4 + 2] = b2; sh[w][128 + lane * 4 + 3] = b3;
    __syncthreads();
    float s = 0.f;
    #pragma unroll
    for (int ww = 0; ww < 8; ww++) s += sh[ww][tid];
    sums[tid] = s;
}

// ---------------- fused prototype EMA update -> int8 + per-class scale ----------------
__global__ __launch_bounds__(256) void k_proto2(
    const float* __restrict__ pf, const float* __restrict__ pr)
{
    __shared__ float sh[256];
    bool fti = blockIdx.x < CF;
    int c = fti ? blockIdx.x : blockIdx.x - CF;
    int C = fti ? CF : CR;
    int n = fti ? g_cnt_f[c] : g_cnt_r[c];
    const float* sums = (fti ? g_sum_f : g_sum_r);
    const float* pin  = (fti ? pf : pr) + c * D;
    int8_t* pout = (fti ? g_pbq_f : g_pbq_r) + c * D;
    float*  psc  = fti ? g_pbs_f : g_pbs_r;

    int t = threadIdx.x;
    float acc = 0.f;
    #pragma unroll
    for (int seg = 0; seg < SEG; seg++)
        acc += sums[((size_t)seg * C + c) * D + t];
    float mv = acc / fmaxf((float)n, 1.f);
    sh[t] = mv * mv;
    __syncthreads();
    #pragma unroll
    for (int o = 128; o; o >>= 1) { if (t < o) sh[t] += sh[t + o]; __syncthreads(); }
    float nm = fmaxf(sqrtf(sh[0]), EPSN);
    __syncthreads();
    mv = mv / nm;
    float p = pin[t];
    float q = 0.5f * p + 0.5f * mv;
    sh[t] = q * q;
    __syncthreads();
    #pragma unroll
    for (int o = 128; o; o >>= 1) { if (t < o) sh[t] += sh[t + o]; __syncthreads(); }
    float nq = fmaxf(sqrtf(sh[0]), EPSN);
    float val = (n > 0) ? q / nq : p;
    __syncthreads();
    sh[t] = fabsf(val);
    __syncthreads();
    #pragma unroll
    for (int o = 128; o; o >>= 1) { if (t < o) sh[t] = fmaxf(sh[t], sh[t + o]); __syncthreads(); }
    float m = fmaxf(sh[0], 1e-30f);
    int qv = __float2int_rn(val * (127.f / m));
    qv = max(-127, min(127, qv));
    pout[t] = (int8_t)qv;
    if (t == 0) psc[c] = m * (1.f / 127.f);
}

// ---------------- int8 mma.sync fused GEMM + softmax CE + inline final ----------------
// smem: 0 lab | 512 scale | 1024 rs | 2048 tg | 3072 red_s | 3104 red_c
//       3136 last-flag | 3200 scb[512]
//       5376 A(34816) | 40192 B0(34816) | 75008 B1(34816) -> 109824 (2 CTA/SM)
#define A_OFF   5376
#define B0_OFF  40192
#define BBUF    34816
#define SMEM_LOSS 109824
#define NBLK_R (NR/128)
#define NBLK_F (NB/128)
#define TOTAL_BLK (NBLK_R + NBLK_F)

__device__ __forceinline__ void prefetch_T(uint32_t sbu, uint32_t dstOff,
                                           const int8_t* __restrict__ P,
                                           int r0, int tid) {
    #pragma unroll
    for (int i = 0; i < 8; i++) {
        int ch = tid + i * 256;
        int r  = ch >> 4;
        int c16 = (ch & 15) * 16;
        uint32_t dst = sbu + dstOff + (uint32_t)(r * 272 + c16);
        const void* src = P + (size_t)(r0 + r) * D + c16;
        asm volatile("cp.async.cg.shared.global [%0], [%1], 16;" :: "r"(dst), "l"(src));
    }
}

__global__ __launch_bounds__(256, 2)
void k_loss_tc(const int* __restrict__ tlab, const int* __restrict__ nlab,
               float* __restrict__ out)
{
    extern __shared__ char smem[];
    int*   lab_sm   = (int*)(smem + 0);
    float* scale_sm = (float*)(smem + 512);
    float* rs_sm    = (float*)(smem + 1024);
    float* tg_sm    = (float*)(smem + 2048);
    float* red_s    = (float*)(smem + 3072);
    float* red_c    = (float*)(smem + 3104);
    int*   last_sm  = (int*)(smem + 3136);
    float* scb_sm   = (float*)(smem + 3200);

    const bool fti = blockIdx.x >= NBLK_R;
    const int  bid = fti ? blockIdx.x - NBLK_R : blockIdx.x;
    const int8_t* Xq = fti ? g_xq_f : g_xq_r;
    const float*  Xs = fti ? g_xs_f : g_xs_r;
    const int8_t* Pq = fti ? g_pbq_f : g_pbq_r;
    const float*  Ps = fti ? g_pbs_f : g_pbs_r;
    const int* lab = fti ? tlab : nlab;
    float* lsum = fti ? g_ls_f : g_ls_r;
    float* lcnt = fti ? g_lc_f : g_lc_r;
    const int NCH = fti ? (CF / 128) : (CR / 128);

    const int tid  = threadIdx.x;
    const int wid  = tid >> 5;
    const int lane = tid & 31;
    const int wr   = wid & 3;
    const int wc   = wid >> 2;
    const int row0 = bid * 128;
    const uint32_t sbu = smem_u32(smem);

    prefetch_T(sbu, A_OFF, Xq, row0, tid);
    prefetch_T(sbu, B0_OFF, Pq, 0, tid);
    CP_COMMIT();
    if (tid < 128) {
        lab_sm[tid]   = lab[row0 + tid];
        scale_sm[tid] = Xs[row0 + tid];
    }
    for (int i = tid; i < NCH * 128; i += 256) scb_sm[i] = Ps[i];
    CP_WAIT0();
    __syncthreads();

    int lb4[4]; float sc4[4];
    #pragma unroll
    for (int mt = 0; mt < 2; mt++)
        #pragma unroll
        for (int h = 0; h < 2; h++) {
            int r = wr * 32 + mt * 16 + (lane >> 2) + h * 8;
            lb4[mt * 2 + h] = lab_sm[r];
            sc4[mt * 2 + h] = scale_sm[r];
        }

    const uint32_t aBase = sbu + A_OFF
        + (uint32_t)(wr * 32 + (lane & 15)) * 272 + (uint32_t)(lane >> 4) * 16;
    const uint32_t bB0 = sbu + B0_OFF
        + (uint32_t)(wc * 64 + (lane & 7) + ((lane >> 4) & 1) * 8) * 272
        + (uint32_t)((lane >> 3) & 1) * 16;

    float ssum[4] = {0.f, 0.f, 0.f, 0.f};
    float tgt[4]  = {0.f, 0.f, 0.f, 0.f};

    for (int c = 0; c < NCH; c++) {
        if (c) { CP_WAIT0(); __syncthreads(); }
        if (c + 1 < NCH) {
            prefetch_T(sbu, B0_OFF + (uint32_t)((c + 1) & 1) * BBUF, Pq, (c + 1) * 128, tid);
            CP_COMMIT();
        }
        const uint32_t bBase = bB0 + (uint32_t)(c & 1) * BBUF;

        int acc[2][8][4];
        #pragma unroll
        for (int mt = 0; mt < 2; mt++)
            #pragma unroll
            for (int nt = 0; nt < 8; nt++)
                #pragma unroll
                for (int e = 0; e < 4; e++) acc[mt][nt][e] = 0;

        #pragma unroll
        for (int k = 0; k < 8; k++) {
            uint32_t aoff = (uint32_t)k * 32;
            uint32_t ah0[4], ah1[4];
            LDSM_X4(ah0, aBase + aoff);
            LDSM_X4(ah1, aBase + 4352 + aoff);
            #pragma unroll
            for (int ntp = 0; ntp < 4; ntp++) {
                uint32_t bh[4];
                LDSM_X4(bh, bBase + (uint32_t)ntp * 4352 + aoff);
                mma_s8(acc[0][ntp*2],   ah0, bh);
                mma_s8(acc[1][ntp*2],   ah1, bh);
                mma_s8(acc[0][ntp*2+1], ah0, bh + 2);
                mma_s8(acc[1][ntp*2+1], ah1, bh + 2);
            }
        }

        int c0 = c * 128;
        #pragma unroll
        for (int nt = 0; nt < 8; nt++) {
            int colb = c0 + wc * 64 + nt * 8 + (lane & 3) * 2;
            float sb0 = scb_sm[colb];
            float sb1 = scb_sm[colb + 1];
            #pragma unroll
            for (int mt = 0; mt < 2; mt++) {
                float l0 = __int2float_rn(acc[mt][nt][0]) * sc4[mt*2]   * sb0;
                float l1 = __int2float_rn(acc[mt][nt][1]) * sc4[mt*2]   * sb1;
                float l2 = __int2float_rn(acc[mt][nt][2]) * sc4[mt*2+1] * sb0;
                float l3 = __int2float_rn(acc[mt][nt][3]) * sc4[mt*2+1] * sb1;
                ssum[mt*2]   += ex2f_fast(l0) + ex2f_fast(l1);
                ssum[mt*2+1] += ex2f_fast(l2) + ex2f_fast(l3);
                if (lb4[mt*2]   == colb)     tgt[mt*2]   = l0;
                if (lb4[mt*2]   == colb + 1) tgt[mt*2]   = l1;
                if (lb4[mt*2+1] == colb)     tgt[mt*2+1] = l2;
                if (lb4[mt*2+1] == colb + 1) tgt[mt*2+1] = l3;
            }
        }
    }

    #pragma unroll
    for (int i = 0; i < 4; i++) {
        ssum[i] += __shfl_xor_sync(0xffffffffu, ssum[i], 1);
        ssum[i] += __shfl_xor_sync(0xffffffffu, ssum[i], 2);
        tgt[i]  += __shfl_xor_sync(0xffffffffu, tgt[i], 1);
        tgt[i]  += __shfl_xor_sync(0xffffffffu, tgt[i], 2);
    }
    if ((lane & 3) == 0) {
        #pragma unroll
        for (int i = 0; i < 4; i++) {
            int r = wr * 32 + (i >> 1) * 16 + (lane >> 2) + (i & 1) * 8;
            rs_sm[r * 2 + wc] = ssum[i];
            tg_sm[r * 2 + wc] = tgt[i];
        }
    }
    __syncthreads();

    float v = 0.f, cn = 0.f;
    if (tid < 128) {
        int lb = lab_sm[tid];
        if (lb >= 0) {
            float S  = rs_sm[tid * 2] + rs_sm[tid * 2 + 1];
            float T2 = tg_sm[tid * 2] + tg_sm[tid * 2 + 1];
            v  = LN2 * (lg2f_fast(S) - T2);
            cn = 1.f;
        }
    }
    #pragma unroll
    for (int o = 16; o; o >>= 1) {
        v  += __shfl_xor_sync(0xffffffffu, v, o);
        cn += __shfl_xor_sync(0xffffffffu, cn, o);
    }
    if (lane == 0) { red_s[wid] = v; red_c[wid] = cn; }
    __syncthreads();
    if (tid == 0) {
        lsum[bid] = red_s[0] + red_s[1] + red_s[2] + red_s[3];
        lcnt[bid] = red_c[0] + red_c[1] + red_c[2] + red_c[3];
        __threadfence();
        int done = atomicAdd(&g_done, 1);
        last_sm[0] = (done == TOTAL_BLK - 1);
    }
    __syncthreads();

    // ---- last CTA reduces all per-block partials and writes the outputs ----
    if (last_sm[0]) {
        float sf = 0.f, cf = 0.f, sr = 0.f, cr = 0.f;
        for (int i = tid; i < NBLK_F; i += 256) { sf += g_ls_f[i]; cf += g_lc_f[i]; }
        for (int i = tid; i < NBLK_R; i += 256) { sr += g_ls_r[i]; cr += g_lc_r[i]; }
        #pragma unroll
        for (int o = 16; o; o >>= 1) {
            sf += __shfl_xor_sync(0xffffffffu, sf, o);
            cf += __shfl_xor_sync(0xffffffffu, cf, o);
            sr += __shfl_xor_sync(0xffffffffu, sr, o);
            cr += __shfl_xor_sync(0xffffffffu, cr, o);
        }
        if (lane == 0) {
            rs_sm[wid * 4 + 0] = sf; rs_sm[wid * 4 + 1] = cf;
            rs_sm[wid * 4 + 2] = sr; rs_sm[wid * 4 + 3] = cr;
        }
        __syncthreads();
        if (tid == 0) {
            float SF = 0.f, CFv = 0.f, SR = 0.f, CRv = 0.f;
            #pragma unroll
            for (int w2 = 0; w2 < 8; w2++) {
                SF  += rs_sm[w2 * 4 + 0];
                CFv += rs_sm[w2 * 4 + 1];
                SR  += rs_sm[w2 * 4 + 2];
                CRv += rs_sm[w2 * 4 + 3];
            }
            out[0] = SF / fmaxf(CFv, 1.f);
            out[1] = SR / fmaxf(CRv, 1.f);
            g_done = 0;   // reset for next graph replay (deterministic)
        }
    }
}

// ---------------- host launcher (graph-capturable, allocation-free) ----------------
extern "C" void kernel_launch(void* const* d_in, const int* in_sizes, int n_in,
                              void* d_out, int out_size) {
    (void)in_sizes; (void)n_in; (void)out_size;
    const float* f_fti = (const float*)d_in[0];
    const float* e_rcl = (const float*)d_in[1];
    const int*   tlab  = (const int*)d_in[2];
    const int*   nlab  = (const int*)d_in[3];
    const float* pf    = (const float*)d_in[4];
    const float* pr    = (const float*)d_in[5];
    float* out = (float*)d_out;

    cudaFuncSetAttribute(k_loss_tc, cudaFuncAttributeMaxDynamicSharedMemorySize, SMEM_LOSS);

    k_histp<<<2 * HB, 256>>>(tlab, nlab);
    k_scan<<<1, 512>>>();
    k_scatter2<<<(NB + NR) / 256, 256>>>(tlab, nlab);
    k_classsum2<<<SEG * (CF + CR), 256>>>(f_fti, e_rcl);
    k_proto2<<<CF + CR, 256>>>(pf, pr);
    k_loss_tc<<<TOTAL_BLK, 256, SMEM_LOSS>>>(tlab, nlab, out);
}